// round 16
// baseline (speedup 1.0000x reference)
#include <cuda_runtime.h>
#include <cuda_bf16.h>
#include <math.h>

#define B_ 64
#define S_ 64
#define T_ 64
#define H_ 1024
#define E_ 1024
#define G_ 3072
#define V_ 32000
#define NSTEP 127
#define NSTEP_PAD 128
#define ASTR 36                      // gru smem row stride (u32 words)
#define AST2 20                      // big-tile smem row stride (u32 words)
#define SA_SZ (64 * ASTR)
#define SW_SZ (24 * ASTR)
#define GRP_WORDS (2 * SA_SZ + 2 * SW_SZ)           // per-group smem block
#define GRU_SMEM_WORDS (4 * GRP_WORDS + 3 * 1600)   // 4 groups + 3 C buffers
#define GRU_SMEM_BYTES (GRU_SMEM_WORDS * 4)
#define BIG_A_WORDS (128 * AST2)                    // per plane
#define BIG_B_WORDS (256 * AST2)
#define BIG_SMEM_WORDS (2 * BIG_A_WORDS + 2 * BIG_B_WORDS)
#define BIG_SMEM_BYTES (BIG_SMEM_WORDS * 4)
#define GH_ ((size_t)G_ * H_)

typedef __nv_bfloat16 bf16;

// ---------------- device-global scratch ----------------
__device__ bf16 g_wr_hi[6ull * G_ * H_];   // 0:Whh_e0 1:Whh_e1 2:Wih_e1 3:Whh_d0 4:Whh_d1 5:Wih_d1
__device__ bf16 g_wr_lo[6ull * G_ * H_];
__device__ bf16 g_wi0_hi[2ull * G_ * H_];  // layer-0 Wih: enc, dec
__device__ bf16 g_wi0_lo[2ull * G_ * H_];
__device__ bf16 g_wout_hi[(size_t)V_ * H_];
__device__ bf16 g_wout_lo[(size_t)V_ * H_];
__device__ bf16 g_x0_hi[(size_t)NSTEP_PAD * B_ * E_];   // padded to 128 steps
__device__ bf16 g_x0_lo[(size_t)NSTEP_PAD * B_ * E_];
__device__ float g_gi0[(size_t)NSTEP_PAD * B_ * G_];
__device__ float g_hf[2][2][B_ * H_];
__device__ bf16 g_h_hi[2][2][B_ * H_];
__device__ bf16 g_h_lo[2][2][B_ * H_];
__device__ bf16 g_xl_hi[B_ * H_];
__device__ bf16 g_xl_lo[B_ * H_];
__device__ bf16 g_top_hi[(size_t)T_ * B_ * H_];
__device__ bf16 g_top_lo[(size_t)T_ * B_ * H_];
__device__ unsigned g_ctr;                 // grid-barrier counter (reset per launch)

__device__ __forceinline__ float sigm(float x) { return 1.0f / (1.0f + expf(-x)); }

__device__ __forceinline__ void split2(float x, bf16& hi, bf16& lo) {
    hi = __float2bfloat16(x);
    lo = __float2bfloat16(x - __bfloat162float(hi));
}

__device__ __forceinline__ void mma_acc(float (&d)[4],
    unsigned a0, unsigned a1, unsigned a2, unsigned a3, unsigned b0, unsigned b1)
{
    asm volatile(
        "mma.sync.aligned.m16n8k16.row.col.f32.bf16.bf16.f32 "
        "{%0,%1,%2,%3},{%4,%5,%6,%7},{%8,%9},{%0,%1,%2,%3};\n"
        : "+f"(d[0]), "+f"(d[1]), "+f"(d[2]), "+f"(d[3])
        : "r"(a0), "r"(a1), "r"(a2), "r"(a3), "r"(b0), "r"(b1));
}

__device__ __forceinline__ void ldsm_x4(unsigned& r0, unsigned& r1, unsigned& r2, unsigned& r3,
                                        unsigned addr)
{
    asm volatile("ldmatrix.sync.aligned.m8n8.x4.shared.b16 {%0,%1,%2,%3}, [%4];"
                 : "=r"(r0), "=r"(r1), "=r"(r2), "=r"(r3) : "r"(addr));
}
__device__ __forceinline__ void ldsm_x2(unsigned& r0, unsigned& r1, unsigned addr)
{
    asm volatile("ldmatrix.sync.aligned.m8n8.x2.shared.b16 {%0,%1}, [%2];"
                 : "=r"(r0), "=r"(r1) : "r"(addr));
}

// software grid barrier: all CTAs co-resident (1 CTA/SM, 128 <= 148 SMs)
__device__ __forceinline__ void grid_barrier(unsigned& bar_no, int nb) {
    __syncthreads();
    __threadfence();
    if (threadIdx.x == 0) {
        const unsigned target = (bar_no + 1u) * (unsigned)nb;
        atomicAdd(&g_ctr, 1u);
        while (*(volatile unsigned*)&g_ctr < target) __nanosleep(64);
    }
    bar_no++;
    __syncthreads();
}

// ---------------- init ----------------
__global__ void init_kernel(float* __restrict__ out) {
    const int idx = blockIdx.x * blockDim.x + threadIdx.x;
    const int stride = gridDim.x * blockDim.x;
    const bf16 z = __float2bfloat16(0.0f);
    if (idx == 0) g_ctr = 0u;
    for (int i = idx; i < B_ * H_; i += stride) {
        g_hf[0][0][i] = 0.0f; g_hf[1][0][i] = 0.0f;
        g_h_hi[0][0][i] = z; g_h_lo[0][0][i] = z;
        g_h_hi[1][0][i] = z; g_h_lo[1][0][i] = z;
    }
    for (int i = idx; i < B_ * V_; i += stride) {
        const int b = i / V_;
        const int v = i - b * V_;
        out[(size_t)b * (T_ * V_) + v] = 0.0f;
    }
}

// ---------------- one-shot weight split (all 9 regions) ----------------
__global__ void __launch_bounds__(256) split_all(
    const float* s0, const float* s1, const float* s2, const float* s3,
    const float* s4, const float* s5, const float* s6, const float* s7,
    const float* s8)
{
    const float* src; bf16* hi; bf16* lo; size_t n = GH_;
    switch (blockIdx.y) {
        case 0: src = s0; hi = g_wr_hi;            lo = g_wr_lo;            break;
        case 1: src = s1; hi = g_wr_hi + GH_;      lo = g_wr_lo + GH_;      break;
        case 2: src = s2; hi = g_wr_hi + 2 * GH_;  lo = g_wr_lo + 2 * GH_;  break;
        case 3: src = s3; hi = g_wr_hi + 3 * GH_;  lo = g_wr_lo + 3 * GH_;  break;
        case 4: src = s4; hi = g_wr_hi + 4 * GH_;  lo = g_wr_lo + 4 * GH_;  break;
        case 5: src = s5; hi = g_wr_hi + 5 * GH_;  lo = g_wr_lo + 5 * GH_;  break;
        case 6: src = s6; hi = g_wi0_hi;           lo = g_wi0_lo;           break;
        case 7: src = s7; hi = g_wi0_hi + GH_;     lo = g_wi0_lo + GH_;     break;
        default: src = s8; hi = g_wout_hi; lo = g_wout_lo; n = (size_t)V_ * H_; break;
    }
    size_t i = (size_t)blockIdx.x * blockDim.x + threadIdx.x;
    const size_t stride = (size_t)gridDim.x * blockDim.x;
    const size_t n4 = n >> 2;
    for (; i < n4; i += stride) {
        const float4 v = ((const float4*)src)[i];
        bf16 h0, l0, h1, l1, h2, l2, h3, l3;
        split2(v.x, h0, l0); split2(v.y, h1, l1);
        split2(v.z, h2, l2); split2(v.w, h3, l3);
        ((__nv_bfloat162*)hi)[2 * i]     = __halves2bfloat162(h0, h1);
        ((__nv_bfloat162*)hi)[2 * i + 1] = __halves2bfloat162(h2, h3);
        ((__nv_bfloat162*)lo)[2 * i]     = __halves2bfloat162(l0, l1);
        ((__nv_bfloat162*)lo)[2 * i + 1] = __halves2bfloat162(l2, l3);
    }
}

// ---------------- embedding gather + split, all 127 steps ----------------
__global__ void gather_all(const int* __restrict__ src_tokens, const int* __restrict__ trg,
                           const float* __restrict__ emb_enc, const float* __restrict__ emb_dec)
{
    const int total = NSTEP * B_ * (E_ / 4);
    int idx = blockIdx.x * blockDim.x + threadIdx.x;
    const int stride = gridDim.x * blockDim.x;
    for (; idx < total; idx += stride) {
        const int q = idx & 255;
        const int rb = idx >> 8;
        const int b = rb & 63;
        const int st = rb >> 6;
        int tok; const float* emb;
        if (st < S_) { tok = src_tokens[b * S_ + st]; emb = emb_enc; }
        else         { tok = trg[b * T_ + (st - S_)]; emb = emb_dec; }
        const float4 v = ((const float4*)(emb + (size_t)tok * E_))[q];
        bf16 h0, l0, h1, l1, h2, l2, h3, l3;
        split2(v.x, h0, l0); split2(v.y, h1, l1);
        split2(v.z, h2, l2); split2(v.w, h3, l3);
        const size_t base = (size_t)rb * E_ + q * 4;
        *(__nv_bfloat162*)(g_x0_hi + base)     = __halves2bfloat162(h0, h1);
        *(__nv_bfloat162*)(g_x0_hi + base + 2) = __halves2bfloat162(h2, h3);
        *(__nv_bfloat162*)(g_x0_lo + base)     = __halves2bfloat162(l0, l1);
        *(__nv_bfloat162*)(g_x0_lo + base + 2) = __halves2bfloat162(l2, l3);
    }
}

// ============ big batched MMA GEMM: 128 x 256 tile, 512 thr (16 warps) =======
// warp tile 32 x 64: wm = w&3 (M strip of 32), wn = w>>2 (N strip of 64).
__device__ __forceinline__ void big_tile_mainloop(
    const bf16* __restrict__ Ahi, const bf16* __restrict__ Alo,
    const bf16* __restrict__ Bhi, const bf16* __restrict__ Blo,
    int n0, unsigned* sm,
    float (&acc)[2][8][4], int tid, int wm, int wn)
{
    unsigned* sA0 = sm;
    unsigned* sA1 = sm + BIG_A_WORDS;
    unsigned* sB0 = sm + 2 * BIG_A_WORDS;
    unsigned* sB1 = sm + 2 * BIG_A_WORDS + BIG_B_WORDS;

    const int lane = tid & 31;
    const int mi = lane >> 3, ri = lane & 7;

    const unsigned sA0b = (unsigned)__cvta_generic_to_shared(sA0);
    const unsigned sA1b = (unsigned)__cvta_generic_to_shared(sA1);
    const unsigned sB0b = (unsigned)__cvta_generic_to_shared(sB0);
    const unsigned sB1b = (unsigned)__cvta_generic_to_shared(sB1);

    unsigned aoff[2];
#pragma unroll
    for (int ma = 0; ma < 2; ma++)
        aoff[ma] = ((wm * 32 + ma * 16 + ri + (mi & 1) * 8) * AST2 + (mi >> 1) * 4) * 4;
    unsigned boff[4];
#pragma unroll
    for (int np = 0; np < 4; np++)
        boff[np] = ((wn * 64 + np * 16 + ri + (mi >> 1) * 8) * AST2 + (mi & 1) * 4) * 4;

    int4 pa[2], pb[4];
    auto ld = [&](int k0) {
#pragma unroll
        for (int it = 0; it < 2; it++) {             // A: 1024 int4 over 512 thr
            const int idx = tid + it * 512;
            const int pl = idx >> 9;
            const int rem = idx & 511;
            const int r = rem >> 2;
            const int q = rem & 3;
            pa[it] = *(const int4*)((pl ? Alo : Ahi) + (size_t)r * H_ + k0 + q * 8);
        }
#pragma unroll
        for (int it = 0; it < 4; it++) {             // B: 2048 int4 over 512 thr
            const int idx = tid + it * 512;
            const int pl = idx >> 10;
            const int rem = idx & 1023;
            const int r = rem >> 2;
            const int q = rem & 3;
            pb[it] = *(const int4*)((pl ? Blo : Bhi) + (size_t)(n0 + r) * H_ + k0 + q * 8);
        }
    };
    auto st = [&]() {
#pragma unroll
        for (int it = 0; it < 2; it++) {
            const int idx = tid + it * 512;
            const int pl = idx >> 9;
            const int rem = idx & 511;
            const int r = rem >> 2;
            const int q = rem & 3;
            *(int4*)&((pl ? sA1 : sA0)[r * AST2 + q * 4]) = pa[it];
        }
#pragma unroll
        for (int it = 0; it < 4; it++) {
            const int idx = tid + it * 512;
            const int pl = idx >> 10;
            const int rem = idx & 1023;
            const int r = rem >> 2;
            const int q = rem & 3;
            *(int4*)&((pl ? sB1 : sB0)[r * AST2 + q * 4]) = pb[it];
        }
    };

    ld(0);
    for (int k0 = 0; k0 < H_; k0 += 32) {
        st();
        __syncthreads();
        if (k0 + 32 < H_) ld(k0 + 32);
#pragma unroll
        for (int ks = 0; ks < 2; ks++) {
            const unsigned kb = ks * 32;
            unsigned ah[2][4], al[2][4];
#pragma unroll
            for (int ma = 0; ma < 2; ma++) {
                ldsm_x4(ah[ma][0], ah[ma][1], ah[ma][2], ah[ma][3], sA0b + aoff[ma] + kb);
                ldsm_x4(al[ma][0], al[ma][1], al[ma][2], al[ma][3], sA1b + aoff[ma] + kb);
            }
#pragma unroll
            for (int np = 0; np < 4; np++) {
                unsigned bh0, bh1, bh2, bh3, bl0, bl1, bl2, bl3;
                ldsm_x4(bh0, bh1, bh2, bh3, sB0b + boff[np] + kb);
                ldsm_x4(bl0, bl1, bl2, bl3, sB1b + boff[np] + kb);
#pragma unroll
                for (int ma = 0; ma < 2; ma++) {
                    mma_acc(acc[ma][np * 2],     ah[ma][0], ah[ma][1], ah[ma][2], ah[ma][3], bh0, bh1);
                    mma_acc(acc[ma][np * 2 + 1], ah[ma][0], ah[ma][1], ah[ma][2], ah[ma][3], bh2, bh3);
                    mma_acc(acc[ma][np * 2],     ah[ma][0], ah[ma][1], ah[ma][2], ah[ma][3], bl0, bl1);
                    mma_acc(acc[ma][np * 2 + 1], ah[ma][0], ah[ma][1], ah[ma][2], ah[ma][3], bl2, bl3);
                    mma_acc(acc[ma][np * 2],     al[ma][0], al[ma][1], al[ma][2], al[ma][3], bh0, bh1);
                    mma_acc(acc[ma][np * 2 + 1], al[ma][0], al[ma][1], al[ma][2], al[ma][3], bh2, bh3);
                }
            }
        }
        __syncthreads();
    }
}

// ---- layer-0 input projection, all steps (2 steps per M-tile) ----
__global__ void __launch_bounds__(512) gi0_all(
    const float* __restrict__ bih_e, const float* __restrict__ bih_d)
{
    extern __shared__ unsigned smem_big[];
    const int bx = blockIdx.x;                  // 64 M-tiles: 0-31 enc, 32-63 dec
    const int n0 = blockIdx.y * 256;
    const int tid = threadIdx.x, w = tid >> 5, lane = tid & 31;
    const int wm = w & 3, wn = w >> 2, g = lane >> 2, c = lane & 3;

    const size_t woff = (bx < 32) ? 0 : GH_;
    const float* bias = (bx < 32) ? bih_e : bih_d;

    float acc[2][8][4];
#pragma unroll
    for (int ma = 0; ma < 2; ma++)
#pragma unroll
        for (int i = 0; i < 8; i++)
#pragma unroll
            for (int j = 0; j < 4; j++) acc[ma][i][j] = 0.0f;

    big_tile_mainloop(g_x0_hi + (size_t)bx * 128 * E_, g_x0_lo + (size_t)bx * 128 * E_,
                      g_wi0_hi + woff, g_wi0_lo + woff, n0, smem_big, acc, tid, wm, wn);

#pragma unroll
    for (int nt = 0; nt < 8; nt++) {
        const int v = n0 + wn * 64 + nt * 8 + 2 * c;
        const float b0 = bias[v], b1 = bias[v + 1];
#pragma unroll
        for (int ma = 0; ma < 2; ma++)
#pragma unroll
            for (int hh = 0; hh < 2; hh++) {
                const size_t rg = (size_t)bx * 128 + wm * 32 + ma * 16 + g + hh * 8;
                float2 r;
                r.x = acc[ma][nt][hh * 2 + 0] + b0;
                r.y = acc[ma][nt][hh * 2 + 1] + b1;
                *(float2*)&g_gi0[rg * G_ + v] = r;
            }
    }
}

// ---- vocab projection (2 steps per M-tile) ----
__global__ void __launch_bounds__(512) out_mma(const float* __restrict__ bout,
                                               float* __restrict__ out)
{
    extern __shared__ unsigned smem_big[];
    const int bx = blockIdx.x;                  // 32 M-tiles
    const int n0 = blockIdx.y * 256;
    const int tid = threadIdx.x, w = tid >> 5, lane = tid & 31;
    const int wm = w & 3, wn = w >> 2, g = lane >> 2, c = lane & 3;

    float acc[2][8][4];
#pragma unroll
    for (int ma = 0; ma < 2; ma++)
#pragma unroll
        for (int i = 0; i < 8; i++)
#pragma unroll
            for (int j = 0; j < 4; j++) acc[ma][i][j] = 0.0f;

    big_tile_mainloop(g_top_hi + (size_t)bx * 128 * H_, g_top_lo + (size_t)bx * 128 * H_,
                      g_wout_hi, g_wout_lo, n0, smem_big, acc, tid, wm, wn);

#pragma unroll
    for (int nt = 0; nt < 8; nt++) {
        const int v = n0 + wn * 64 + nt * 8 + 2 * c;
        const float b0 = __ldg(bout + v), b1 = __ldg(bout + v + 1);
#pragma unroll
        for (int ma = 0; ma < 2; ma++)
#pragma unroll
            for (int hh = 0; hh < 2; hh++) {
                const int rg = bx * 128 + wm * 32 + ma * 16 + g + hh * 8;
                const int s = rg >> 6, b = rg & 63;
                if (s < T_ - 1) {
                    float2 r;
                    r.x = acc[ma][nt][hh * 2 + 0] + b0;
                    r.y = acc[ma][nt][hh * 2 + 1] + b1;
                    *(float2*)&out[(size_t)b * (T_ * V_) + (size_t)(s + 1) * V_ + v] = r;
                }
            }
    }
}

// ================= recurrent GEMM pass (A loads L2-coherent) =================
__device__ __forceinline__ void gru_pass2(
    const bf16* __restrict__ Ahi, const bf16* __restrict__ Alo,
    const bf16* __restrict__ Whi, const bf16* __restrict__ Wlo,
    int j0, int kbase, int nchunks,
    unsigned* sA0, unsigned* sA1, unsigned* sW0, unsigned* sW1,
    float (&acc)[3][4], int tg, int m0)
{
    const int lane = tg & 31;
    const int mi = lane >> 3, ri = lane & 7;

    const unsigned sA0b = (unsigned)__cvta_generic_to_shared(sA0);
    const unsigned sA1b = (unsigned)__cvta_generic_to_shared(sA1);
    const unsigned sW0b = (unsigned)__cvta_generic_to_shared(sW0);
    const unsigned sW1b = (unsigned)__cvta_generic_to_shared(sW1);

    const unsigned aoff  = ((m0 + ri + (mi & 1) * 8) * ASTR + (mi >> 1) * 4) * 4;
    const unsigned w4off = ((ri + (mi >> 1) * 8) * ASTR + (mi & 1) * 4) * 4;
    const unsigned w2off = ((16 + ri) * ASTR + ((lane >> 3) & 1) * 4) * 4;

    int4 pa[8], pw[3];
    auto ld = [&](int k0) {
#pragma unroll
        for (int it = 0; it < 8; it++) {
            const int idx = tg + it * 128;
            const int pl = idx >> 9;
            const int rem = idx & 511;
            const int r = rem >> 3, q = rem & 7;
            pa[it] = __ldcg((const int4*)((pl ? Alo : Ahi) + (size_t)r * H_ + k0 + q * 8));
        }
#pragma unroll
        for (int it = 0; it < 3; it++) {
            const int idx = tg + it * 128;
            const int pl = (idx >= 192) ? 1 : 0;
            const int i = idx - 192 * pl;
            const int r = i >> 3, q = i & 7;
            const int grow = (r >> 3) * H_ + j0 + (r & 7);
            pw[it] = *(const int4*)((pl ? Wlo : Whi) + (size_t)grow * H_ + k0 + q * 8);
        }
    };
    auto st = [&]() {
#pragma unroll
        for (int it = 0; it < 8; it++) {
            const int idx = tg + it * 128;
            const int pl = idx >> 9;
            const int rem = idx & 511;
            const int r = rem >> 3, q = rem & 7;
            *(int4*)&((pl ? sA1 : sA0)[r * ASTR + q * 4]) = pa[it];
        }
#pragma unroll
        for (int it = 0; it < 3; it++) {
            const int idx = tg + it * 128;
            const int pl = (idx >= 192) ? 1 : 0;
            const int i = idx - 192 * pl;
            const int r = i >> 3, q = i & 7;
            *(int4*)&((pl ? sW1 : sW0)[r * ASTR + q * 4]) = pw[it];
        }
    };

    ld(kbase);
    for (int ch = 0; ch < nchunks; ch++) {
        st();
        __syncthreads();
        if (ch + 1 < nchunks) ld(kbase + (ch + 1) * 64);
#pragma unroll
        for (int ks = 0; ks < 4; ks++) {
            const unsigned kb = ks * 32;
            unsigned ah0, ah1, ah2, ah3, al0, al1, al2, al3;
            ldsm_x4(ah0, ah1, ah2, ah3, sA0b + aoff + kb);
            ldsm_x4(al0, al1, al2, al3, sA1b + aoff + kb);
            unsigned bh0, bh1, bh2, bh3, bl0, bl1, bl2, bl3;
            unsigned ch0, ch1, cl0, cl1;
            ldsm_x4(bh0, bh1, bh2, bh3, sW0b + w4off + kb);
            ldsm_x4(bl0, bl1, bl2, bl3, sW1b + w4off + kb);
            ldsm_x2(ch0, ch1, sW0b + w2off + kb);
            ldsm_x2(cl0, cl1, sW1b + w2off + kb);
            mma_acc(acc[0], ah0, ah1, ah2, ah3, bh0, bh1);
            mma_acc(acc[1], ah0, ah1, ah2, ah3, bh2, bh3);
            mma_acc(acc[2], ah0, ah1, ah2, ah3, ch0, ch1);
            mma_acc(acc[0], ah0, ah1, ah2, ah3, bl0, bl1);
            mma_acc(acc[1], ah0, ah1, ah2, ah3, bl2, bl3);
            mma_acc(acc[2], ah0, ah1, ah2, ah3, cl0, cl1);
            mma_acc(acc[0], al0, al1, al2, al3, bh0, bh1);
            mma_acc(acc[1], al0, al1, al2, al3, bh2, bh3);
            mma_acc(acc[2], al0, al1, al2, al3, ch0, ch1);
        }
        __syncthreads();
    }
}

// C dump layout: C[b*25 + gate*8 + jj]
__device__ __forceinline__ void dump_frag(float* C, float (&acc)[3][4], int m0, int g, int c) {
#pragma unroll
    for (int nt = 0; nt < 3; nt++)
#pragma unroll
        for (int v = 0; v < 4; v++) {
            const int b = m0 + g + ((v >> 1) << 3);
            const int jj = 2 * c + (v & 1);
            C[b * 25 + nt * 8 + jj] = acc[nt][v];
        }
}

// ================= persistent recurrence: all 127 steps, one launch ==========
__global__ void __launch_bounds__(512) gru_persist(
    const float* __restrict__ bhh_e0, const float* __restrict__ bih_e1,
    const float* __restrict__ bhh_e1,
    const float* __restrict__ bhh_d0, const float* __restrict__ bih_d1,
    const float* __restrict__ bhh_d1,
    const int* __restrict__ src_lengths)
{
    extern __shared__ unsigned smem_u[];
    const int tid = threadIdx.x;
    const int grp = tid >> 7;              // 0..3
    const int tg = tid & 127;
    const int w2 = tg >> 5, lane = tid & 31;
    const int g = lane >> 2, c = lane & 3, m0 = w2 * 16;
    const int j0 = blockIdx.x * 8;
    const int nb = gridDim.x;

    unsigned* gbase = smem_u + grp * GRP_WORDS;
    unsigned* sA0 = gbase;
    unsigned* sA1 = gbase + SA_SZ;
    unsigned* sW0 = gbase + 2 * SA_SZ;
    unsigned* sW1 = gbase + 2 * SA_SZ + SW_SZ;
    float* C = (float*)(smem_u + 4 * GRP_WORDS);

    unsigned bar_no = 0;

    for (int st = 0; st < NSTEP; st++) {
        const bool enc = (st < S_);
        const int par = st & 1;

        // ---------- layer 0: gh = h0 @ Whh0^T, 4-way k-split ----------
        {
            const size_t woff = enc ? (size_t)0 : 3 * GH_;
            const float* bhh = enc ? bhh_e0 : bhh_d0;

            float acc[3][4];
#pragma unroll
            for (int i = 0; i < 3; i++)
#pragma unroll
                for (int j = 0; j < 4; j++) acc[i][j] = 0.0f;

            gru_pass2(g_h_hi[0][par], g_h_lo[0][par], g_wr_hi + woff, g_wr_lo + woff,
                      j0, grp * 256, 4, sA0, sA1, sW0, sW1, acc, tg, m0);

            if (grp > 0) dump_frag(C + (grp - 1) * 1600, acc, m0, g, c);
            __syncthreads();

            if (grp == 0) {
                const float* hf = g_hf[0][par];
                float* hfn = g_hf[0][par ^ 1];
#pragma unroll
                for (int v = 0; v < 4; v++) {
                    const int b = m0 + g + ((v >> 1) << 3);
                    const int jj = 2 * c + (v & 1);
                    const int j = j0 + jj;
                    const float a_r = acc[0][v] + C[b * 25 + jj]      + C[1600 + b * 25 + jj]      + C[3200 + b * 25 + jj];
                    const float a_z = acc[1][v] + C[b * 25 + 8 + jj]  + C[1600 + b * 25 + 8 + jj]  + C[3200 + b * 25 + 8 + jj];
                    const float a_n = acc[2][v] + C[b * 25 + 16 + jj] + C[1600 + b * 25 + 16 + jj] + C[3200 + b * 25 + 16 + jj];
                    const size_t gb = ((size_t)st * B_ + b) * G_;
                    const float r = sigm(g_gi0[gb + j] + a_r + bhh[j]);
                    const float z = sigm(g_gi0[gb + H_ + j] + a_z + bhh[H_ + j]);
                    const float n = tanhf(g_gi0[gb + 2 * H_ + j] + r * (a_n + bhh[2 * H_ + j]));
                    const float hprev = __ldcg(&hf[b * H_ + j]);
                    const float hnew = (1.0f - z) * n + z * hprev;
                    bf16 xh, xl; split2(hnew, xh, xl);
                    g_xl_hi[b * H_ + j] = xh; g_xl_lo[b * H_ + j] = xl;
                    float hs = hnew;
                    if (enc && st >= src_lengths[b]) hs = hprev;
                    hfn[b * H_ + j] = hs;
                    bf16 sh, sl; split2(hs, sh, sl);
                    g_h_hi[0][par ^ 1][b * H_ + j] = sh;
                    g_h_lo[0][par ^ 1][b * H_ + j] = sl;
                }
            }
        }
        grid_barrier(bar_no, nb);

        // ---------- layer 1: (gi, gh) x (2 k-halves) over 4 groups ----------
        {
            const size_t woffi = enc ? 2 * GH_ : 5 * GH_;
            const size_t woffh = enc ? 1 * GH_ : 4 * GH_;
            const float* bih = enc ? bih_e1 : bih_d1;
            const float* bhh = enc ? bhh_e1 : bhh_d1;

            const bf16 *Ahi, *Alo, *Whi, *Wlo;
            if (grp < 2) {
                Ahi = g_xl_hi; Alo = g_xl_lo;
                Whi = g_wr_hi + woffi; Wlo = g_wr_lo + woffi;
            } else {
                Ahi = g_h_hi[1][par]; Alo = g_h_lo[1][par];
                Whi = g_wr_hi + woffh; Wlo = g_wr_lo + woffh;
            }
            const int kbase = (grp & 1) * 512;

            float acc[3][4];
#pragma unroll
            for (int i = 0; i < 3; i++)
#pragma unroll
                for (int j = 0; j < 4; j++) acc[i][j] = 0.0f;

            gru_pass2(Ahi, Alo, Whi, Wlo, j0, kbase, 8, sA0, sA1, sW0, sW1, acc, tg, m0);

            if (grp > 0) dump_frag(C + (grp - 1) * 1600, acc, m0, g, c);
            __syncthreads();

            if (grp == 0) {
                const float* hf = g_hf[1][par];
                float* hfn = g_hf[1][par ^ 1];
#pragma unroll
                for (int v = 0; v < 4; v++) {
                    const int b = m0 + g + ((v >> 1) << 3);
                    const int jj = 2 * c + (v & 1);
                    const int j = j0 + jj;
                    const float gir = acc[0][v] + C[b * 25 + jj];
                    const float giz = acc[1][v] + C[b * 25 + 8 + jj];
                    const float gin = acc[2][v] + C[b * 25 + 16 + jj];
                    const float ghr = C[1600 + b * 25 + jj]      + C[3200 + b * 25 + jj];
                    const float ghz = C[1600 + b * 25 + 8 + jj]  + C[3200 + b * 25 + 8 + jj];
                    const float ghn = C[1600 + b * 25 + 16 + jj] + C[3200 + b * 25 + 16 + jj];
                    const float r = sigm(gir + bih[j] + ghr + bhh[j]);
                    const float z = sigm(giz + bih[H_ + j] + ghz + bhh[H_ + j]);
                    const float n = tanhf(gin + bih[2 * H_ + j] + r * (ghn + bhh[2 * H_ + j]));
                    const float hprev = __ldcg(&hf[b * H_ + j]);
                    const float hnew = (1.0f - z) * n + z * hprev;
                    if (!enc) {
                        const int step = st - S_;
                        bf16 th, tl; split2(hnew, th, tl);
                        g_top_hi[((size_t)step * B_ + b) * H_ + j] = th;
                        g_top_lo[((size_t)step * B_ + b) * H_ + j] = tl;
                    }
                    float hs = hnew;
                    if (enc && st >= src_lengths[b]) hs = hprev;
                    hfn[b * H_ + j] = hs;
                    bf16 sh, sl; split2(hs, sh, sl);
                    g_h_hi[1][par ^ 1][b * H_ + j] = sh;
                    g_h_lo[1][par ^ 1][b * H_ + j] = sl;
                }
            }
        }
        grid_barrier(bar_no, nb);
    }
}

// ------------------------------- host driver ---------------------------------
extern "C" void kernel_launch(void* const* d_in, const int* in_sizes, int n_in,
                              void* d_out, int out_size) {
    (void)in_sizes; (void)n_in; (void)out_size;
    const int*   src_tokens  = (const int*)d_in[0];
    const int*   src_lengths = (const int*)d_in[1];
    const int*   trg         = (const int*)d_in[2];
    const float* emb_enc = (const float*)d_in[3];
    const float* Wih_enc = (const float*)d_in[4];
    const float* Whh_enc = (const float*)d_in[5];
    const float* bih_enc = (const float*)d_in[6];
    const float* bhh_enc = (const float*)d_in[7];
    const float* emb_dec = (const float*)d_in[8];
    const float* Wih_dec = (const float*)d_in[9];
    const float* Whh_dec = (const float*)d_in[10];
    const float* bih_dec = (const float*)d_in[11];
    const float* bhh_dec = (const float*)d_in[12];
    const float* Wout    = (const float*)d_in[13];
    const float* bout    = (const float*)d_in[14];
    float* out = (float*)d_out;

    cudaFuncSetAttribute(gru_persist, cudaFuncAttributeMaxDynamicSharedMemorySize, GRU_SMEM_BYTES);
    cudaFuncSetAttribute(gi0_all, cudaFuncAttributeMaxDynamicSharedMemorySize, BIG_SMEM_BYTES);
    cudaFuncSetAttribute(out_mma, cudaFuncAttributeMaxDynamicSharedMemorySize, BIG_SMEM_BYTES);

    init_kernel<<<512, 256>>>(out);
    split_all<<<dim3(512, 9), 256>>>(Whh_enc, Whh_enc + GH_, Wih_enc + GH_,
                                     Whh_dec, Whh_dec + GH_, Wih_dec + GH_,
                                     Wih_enc, Wih_dec, Wout);
    gather_all<<<2048, 256>>>(src_tokens, trg, emb_enc, emb_dec);
    gi0_all<<<dim3(64, G_ / 256), 512, BIG_SMEM_BYTES>>>(bih_enc, bih_dec);

    // entire recurrence: ONE launch, 128 co-resident CTAs, software grid barriers
    gru_persist<<<H_ / 8, 512, GRU_SMEM_BYTES>>>(
        bhh_enc, bih_enc + G_, bhh_enc + G_,
        bhh_dec, bih_dec + G_, bhh_dec + G_,
        src_lengths);

    // x = M-tiles fastest -> co-scheduled CTAs share the Wout slice in L2
    out_mma<<<dim3(32, V_ / 256), 512, BIG_SMEM_BYTES>>>(bout, out);
}